// round 9
// baseline (speedup 1.0000x reference)
#include <cuda_runtime.h>
#include <cuda_bf16.h>
#include <cstdint>

#define NN   100000
#define DEG  8
#define HH   128
#define KTOT 1024          // DEG*HH
#define NOUT 384           // 3*HH

// ---------------- device scratch ----------------
__device__ float g_cag[(size_t)NN * HH];                       // 51.2 MB
__device__ __align__(16) __nv_bfloat16 g_w1hi[DEG * HH * HH];  // Uf^T  [d][n][k]
__device__ __align__(16) __nv_bfloat16 g_w1lo[DEG * HH * HH];
__device__ __align__(16) __nv_bfloat16 g_w2hi[NOUT * KTOT];    // Ua^T  [n'][k] interleaved
__device__ __align__(16) __nv_bfloat16 g_w2lo[NOUT * KTOT];

// ---------------- helpers ----------------
static __device__ __forceinline__ uint32_t smem_u32(const void* p) {
    uint32_t a;
    asm("{ .reg .u64 t; cvta.to.shared.u64 t, %1; cvt.u32.u64 %0, t; }" : "=r"(a) : "l"(p));
    return a;
}
static __device__ __forceinline__ void ldmx4(uint32_t r[4], uint32_t addr) {
    asm volatile("ldmatrix.sync.aligned.m8n8.x4.shared.b16 {%0,%1,%2,%3}, [%4];"
                 : "=r"(r[0]), "=r"(r[1]), "=r"(r[2]), "=r"(r[3]) : "r"(addr));
}
static __device__ __forceinline__ void mma16816(float c[4], const uint32_t a[4], const uint32_t b[2]) {
    asm volatile("mma.sync.aligned.m16n8k16.row.col.f32.bf16.bf16.f32 "
                 "{%0,%1,%2,%3},{%4,%5,%6,%7},{%8,%9},{%0,%1,%2,%3};"
                 : "+f"(c[0]), "+f"(c[1]), "+f"(c[2]), "+f"(c[3])
                 : "r"(a[0]), "r"(a[1]), "r"(a[2]), "r"(a[3]), "r"(b[0]), "r"(b[1]));
}
static __device__ __forceinline__ void cp16(uint32_t dst, const void* src) {
    asm volatile("cp.async.cg.shared.global [%0], [%1], 16;"
                 :: "r"(dst), "l"(__cvta_generic_to_global(src)) : "memory");
}
#define CP_COMMIT() asm volatile("cp.async.commit_group;" ::: "memory")
#define CP_WAIT0()  asm volatile("cp.async.wait_group 0;" ::: "memory")

static __device__ __forceinline__ float sigm(float x) { return 1.f / (1.f + __expf(-x)); }
static __device__ __forceinline__ void split_bf16(float x, uint32_t& h, uint32_t& l) {
    __nv_bfloat16 hb = __float2bfloat16(x);
    __nv_bfloat16 lb = __float2bfloat16(x - __bfloat162float(hb));
    h = (uint32_t)__bfloat16_as_ushort(hb);
    l = (uint32_t)__bfloat16_as_ushort(lb);
}
static __device__ __forceinline__ void pack2(float a, float b, uint32_t& ph, uint32_t& pl) {
    uint32_t ha, la, hb, lb;
    split_bf16(a, ha, la); split_bf16(b, hb, lb);
    ph = ha | (hb << 16);
    pl = la | (lb << 16);
}

// ---------------- prep ----------------
__global__ void prep_weights(const float* __restrict__ Uf, const float* __restrict__ Ua) {
    int t = blockIdx.x * blockDim.x + threadIdx.x;
    if (t < DEG * HH * HH) {                 // W1: [d][n][k] = Uf[d][k][n]
        int k = t & 127, n = (t >> 7) & 127, d = t >> 14;
        float v = Uf[((size_t)d * HH + k) * HH + n];
        uint32_t h, l; split_bf16(v, h, l);
        g_w1hi[t] = __ushort_as_bfloat16((unsigned short)h);
        g_w1lo[t] = __ushort_as_bfloat16((unsigned short)l);
        return;
    }
    int u = t - DEG * HH * HH;
    if (u < NOUT * KTOT) {                   // W2: n' = grp*24 + ch*8 + c8
        int k = u & 1023, np = u >> 10;
        int grp = np / 24, rem = np - grp * 24;
        int ch = rem >> 3, c8 = rem & 7;
        int col = grp * 8 + c8;
        int d = k >> 7, h = k & 127;
        float v = Ua[((size_t)d * HH + h) * NOUT + ch * HH + col];
        uint32_t hh_, ll_; split_bf16(v, hh_, ll_);
        g_w2hi[u] = __ushort_as_bfloat16((unsigned short)hh_);
        g_w2lo[u] = __ushort_as_bfloat16((unsigned short)ll_);
    }
}

// =====================================================================
// Kernel 1: f/c_aggr.  384 thr (12 warps: 3m x 4n), M=96, N=128, warp 32x32.
// K loop: 32 chunks of 32; d = kc>>2; f epilogue per d -> reg cag -> g_cag.
// =====================================================================
#define K1_BST   80
#define K1_SBH   0          // B hi 128*80 = 10240
#define K1_SBL   10240
#define K1_SAH   20480      // A hi 96*80 = 7680
#define K1_SAL   28160
#define K1_STAGE 35840
#define K1_SMEM  71680

__global__ __launch_bounds__(384, 1)
void k1_caggr(const float* __restrict__ nh, const float* __restrict__ ncv,
              const float* __restrict__ f_in, const float* __restrict__ bf) {
    extern __shared__ unsigned char smb[];
    const uint32_t sb = smem_u32(smb);
    const int tid = threadIdx.x, wid = tid >> 5, l = tid & 31;
    const int wm = wid >> 2, wn = wid & 3;       // wm in 0..2 (3 m-warps), wn in 0..3
    const int nb = blockIdx.x * 96;

    uint32_t aoff[2], boff[2];
#pragma unroll
    for (int fm = 0; fm < 2; fm++)
        aoff[fm] = (uint32_t)(wm * 32 + fm * 16 + (l & 15)) * K1_BST + (uint32_t)(l >> 4) * 16;
#pragma unroll
    for (int p = 0; p < 2; p++)
        boff[p] = (uint32_t)(wn * 32 + p * 16 + (l & 7) + ((l >> 4) ? 8 : 0)) * K1_BST
                + (uint32_t)((l >> 3) & 1) * 16;

    float accf[2][4][4], cag[2][4][4];
#pragma unroll
    for (int a = 0; a < 2; a++)
#pragma unroll
        for (int b = 0; b < 4; b++)
#pragma unroll
            for (int c = 0; c < 4; c++) { accf[a][b][c] = 0.f; cag[a][b][c] = 0.f; }

    const int arow = tid >> 2, aq = tid & 3;     // 96 rows x 4 quads
    const int anode = nb + arow;
    const float* asrc = nh + (size_t)anode * KTOT + aq * 8;

    // ---- prologue: chunk 0 ----
    {
#pragma unroll
        for (int i = 0; i < 2; i++) {
            int idx = tid + i * 384;             // B: 512 granule-pairs
            if (idx < 512) {
                int r = idx >> 2, g = idx & 3;
                uint32_t doff = sb + r * K1_BST + g * 16;
                cp16(doff + K1_SBH, (const char*)(g_w1hi + (size_t)r * HH) + g * 16);
                cp16(doff + K1_SBL, (const char*)(g_w1lo + (size_t)r * HH) + g * 16);
            }
        }
        CP_COMMIT();
        float4 v0 = make_float4(0,0,0,0), v1 = v0;
        if (anode < NN) { v0 = *(const float4*)(asrc); v1 = *(const float4*)(asrc + 4); }
        uint32_t h[4], lo[4];
        pack2(v0.x, v0.y, h[0], lo[0]); pack2(v0.z, v0.w, h[1], lo[1]);
        pack2(v1.x, v1.y, h[2], lo[2]); pack2(v1.z, v1.w, h[3], lo[3]);
        uint32_t ad = sb + K1_SAH + arow * K1_BST + aq * 16;
        asm volatile("st.shared.v4.b32 [%0], {%1,%2,%3,%4};" :: "r"(ad), "r"(h[0]), "r"(h[1]), "r"(h[2]), "r"(h[3]) : "memory");
        asm volatile("st.shared.v4.b32 [%0], {%1,%2,%3,%4};" :: "r"(ad + (K1_SAL - K1_SAH)), "r"(lo[0]), "r"(lo[1]), "r"(lo[2]), "r"(lo[3]) : "memory");
        CP_WAIT0();
        __syncthreads();
    }

    for (int kc = 0; kc < 32; kc++) {
        const uint32_t cur = sb + (kc & 1) * K1_STAGE;
        const uint32_t nxt = sb + ((kc + 1) & 1) * K1_STAGE;
        const bool have_next = (kc < 31);

        float4 v0, v1;
        if (have_next) {
            v0 = make_float4(0,0,0,0); v1 = v0;
            if (anode < NN) {
                v0 = *(const float4*)(asrc + (kc + 1) * 32);
                v1 = *(const float4*)(asrc + (kc + 1) * 32 + 4);
            }
            int dn = (kc + 1) >> 2, sl = (kc + 1) & 3;
#pragma unroll
            for (int i = 0; i < 2; i++) {
                int idx = tid + i * 384;
                if (idx < 512) {
                    int r = idx >> 2, g = idx & 3;
                    uint32_t doff = nxt + r * K1_BST + g * 16;
                    cp16(doff + K1_SBH, (const char*)(g_w1hi + ((size_t)dn * HH + r) * HH) + sl * 64 + g * 16);
                    cp16(doff + K1_SBL, (const char*)(g_w1lo + ((size_t)dn * HH + r) * HH) + sl * 64 + g * 16);
                }
            }
            CP_COMMIT();
        }

        // ---- compute chunk kc ----
#pragma unroll
        for (int ks = 0; ks < 2; ks++) {
            uint32_t ah[2][4], al[2][4];
#pragma unroll
            for (int fm = 0; fm < 2; fm++) {
                ldmx4(ah[fm], cur + K1_SAH + aoff[fm] + ks * 32);
                ldmx4(al[fm], cur + K1_SAL + aoff[fm] + ks * 32);
            }
#pragma unroll
            for (int p = 0; p < 2; p++) {
                uint32_t rh4[4], rl4[4];
                ldmx4(rh4, cur + K1_SBH + boff[p] + ks * 32);
                ldmx4(rl4, cur + K1_SBL + boff[p] + ks * 32);
#pragma unroll
                for (int fm = 0; fm < 2; fm++) {
                    mma16816(accf[fm][p*2+0], ah[fm], rh4 + 0);
                    mma16816(accf[fm][p*2+0], ah[fm], rl4 + 0);
                    mma16816(accf[fm][p*2+0], al[fm], rh4 + 0);
                    mma16816(accf[fm][p*2+1], ah[fm], rh4 + 2);
                    mma16816(accf[fm][p*2+1], ah[fm], rl4 + 2);
                    mma16816(accf[fm][p*2+1], al[fm], rh4 + 2);
                }
            }
        }

        // ---- f epilogue at end of each d ----
        if ((kc & 3) == 3) {
            const int d = kc >> 2;
#pragma unroll
            for (int fm = 0; fm < 2; fm++)
#pragma unroll
                for (int rh = 0; rh < 2; rh++) {
                    int node = nb + wm * 32 + fm * 16 + (l >> 2) + rh * 8;
                    if (node < NN) {
#pragma unroll
                        for (int fn = 0; fn < 4; fn++) {
                            int col = wn * 32 + fn * 8 + (l & 3) * 2;
                            float2 fi  = *(const float2*)(f_in + (size_t)node * HH + col);
                            float2 nc2 = *(const float2*)(ncv + ((size_t)node * DEG + d) * HH + col);
                            float2 bf2 = *(const float2*)(bf + d * HH + col);
                            cag[fm][fn][rh*2+0] += sigm(accf[fm][fn][rh*2+0] + bf2.x + fi.x) * nc2.x;
                            cag[fm][fn][rh*2+1] += sigm(accf[fm][fn][rh*2+1] + bf2.y + fi.y) * nc2.y;
                        }
                    }
#pragma unroll
                    for (int fn = 0; fn < 4; fn++) {
                        accf[fm][fn][rh*2+0] = 0.f;
                        accf[fm][fn][rh*2+1] = 0.f;
                    }
                }
        }

        if (have_next) {
            uint32_t h[4], lo[4];
            pack2(v0.x, v0.y, h[0], lo[0]); pack2(v0.z, v0.w, h[1], lo[1]);
            pack2(v1.x, v1.y, h[2], lo[2]); pack2(v1.z, v1.w, h[3], lo[3]);
            uint32_t ad = nxt + K1_SAH + arow * K1_BST + aq * 16;
            asm volatile("st.shared.v4.b32 [%0], {%1,%2,%3,%4};" :: "r"(ad), "r"(h[0]), "r"(h[1]), "r"(h[2]), "r"(h[3]) : "memory");
            asm volatile("st.shared.v4.b32 [%0], {%1,%2,%3,%4};" :: "r"(ad + (K1_SAL - K1_SAH)), "r"(lo[0]), "r"(lo[1]), "r"(lo[2]), "r"(lo[3]) : "memory");
            CP_WAIT0();
            __syncthreads();
        }
    }

    // ---- store c_aggr ----
#pragma unroll
    for (int fm = 0; fm < 2; fm++)
#pragma unroll
        for (int rh = 0; rh < 2; rh++) {
            int node = nb + wm * 32 + fm * 16 + (l >> 2) + rh * 8;
            if (node >= NN) continue;
#pragma unroll
            for (int fn = 0; fn < 4; fn++) {
                int col = wn * 32 + fn * 8 + (l & 3) * 2;
                *(float2*)(g_cag + (size_t)node * HH + col) =
                    make_float2(cag[fm][fn][rh*2+0], cag[fm][fn][rh*2+1]);
            }
        }
}

// =====================================================================
// Kernel 2: iou GEMM + epilogue.  384 thr (12 warps: 3m x 4n), M=96,
// N=384 full (warp tile 32x96).  nh read once.
// =====================================================================
#define K2_BST   80
#define K2_SBH   0          // B hi 384*80 = 30720
#define K2_SBL   30720
#define K2_SAH   61440      // A hi 96*80 = 7680
#define K2_SAL   69120
#define K2_STAGE 76800
#define K2_SMEM  153600

__global__ __launch_bounds__(384, 1)
void k2_iou(const float* __restrict__ nh, const float* __restrict__ iou_in,
            const float* __restrict__ ba, float* __restrict__ out) {
    extern __shared__ unsigned char smb[];
    const uint32_t sb = smem_u32(smb);
    const int tid = threadIdx.x, wid = tid >> 5, l = tid & 31;
    const int wm = wid >> 2, wn = wid & 3;       // wm in 0..2, wn in 0..3
    const int nb = blockIdx.x * 96;

    uint32_t aoff[2], boff[6];
#pragma unroll
    for (int fm = 0; fm < 2; fm++)
        aoff[fm] = (uint32_t)(wm * 32 + fm * 16 + (l & 15)) * K2_BST + (uint32_t)(l >> 4) * 16;
#pragma unroll
    for (int p = 0; p < 6; p++)
        boff[p] = (uint32_t)(wn * 96 + p * 16 + (l & 7) + ((l >> 4) ? 8 : 0)) * K2_BST
                + (uint32_t)((l >> 3) & 1) * 16;

    float acc[2][12][4];
#pragma unroll
    for (int a = 0; a < 2; a++)
#pragma unroll
        for (int b = 0; b < 12; b++)
#pragma unroll
            for (int c = 0; c < 4; c++) acc[a][b][c] = 0.f;

    const int arow = tid >> 2, aq = tid & 3;
    const int anode = nb + arow;
    const float* asrc = nh + (size_t)anode * KTOT + aq * 8;

    // ---- prologue: chunk 0 ----
    {
#pragma unroll
        for (int i = 0; i < 4; i++) {
            int idx = tid + i * 384;             // B: 1536 granule-pairs
            int r = idx >> 2, g = idx & 3;
            uint32_t doff = sb + r * K2_BST + g * 16;
            cp16(doff + K2_SBH, (const char*)(g_w2hi + (size_t)r * KTOT) + g * 16);
            cp16(doff + K2_SBL, (const char*)(g_w2lo + (size_t)r * KTOT) + g * 16);
        }
        CP_COMMIT();
        float4 v0 = make_float4(0,0,0,0), v1 = v0;
        if (anode < NN) { v0 = *(const float4*)(asrc); v1 = *(const float4*)(asrc + 4); }
        uint32_t h[4], lo[4];
        pack2(v0.x, v0.y, h[0], lo[0]); pack2(v0.z, v0.w, h[1], lo[1]);
        pack2(v1.x, v1.y, h[2], lo[2]); pack2(v1.z, v1.w, h[3], lo[3]);
        uint32_t ad = sb + K2_SAH + arow * K2_BST + aq * 16;
        asm volatile("st.shared.v4.b32 [%0], {%1,%2,%3,%4};" :: "r"(ad), "r"(h[0]), "r"(h[1]), "r"(h[2]), "r"(h[3]) : "memory");
        asm volatile("st.shared.v4.b32 [%0], {%1,%2,%3,%4};" :: "r"(ad + (K2_SAL - K2_SAH)), "r"(lo[0]), "r"(lo[1]), "r"(lo[2]), "r"(lo[3]) : "memory");
        CP_WAIT0();
        __syncthreads();
    }

    for (int kc = 0; kc < 32; kc++) {
        const uint32_t cur = sb + (kc & 1) * K2_STAGE;
        const uint32_t nxt = sb + ((kc + 1) & 1) * K2_STAGE;
        const bool have_next = (kc < 31);

        float4 v0, v1;
        if (have_next) {
            v0 = make_float4(0,0,0,0); v1 = v0;
            if (anode < NN) {
                v0 = *(const float4*)(asrc + (kc + 1) * 32);
                v1 = *(const float4*)(asrc + (kc + 1) * 32 + 4);
            }
#pragma unroll
            for (int i = 0; i < 4; i++) {
                int idx = tid + i * 384;
                int r = idx >> 2, g = idx & 3;
                uint32_t doff = nxt + r * K2_BST + g * 16;
                cp16(doff + K2_SBH, (const char*)(g_w2hi + (size_t)r * KTOT) + (kc + 1) * 64 + g * 16);
                cp16(doff + K2_SBL, (const char*)(g_w2lo + (size_t)r * KTOT) + (kc + 1) * 64 + g * 16);
            }
            CP_COMMIT();
        }

        // ---- compute ----
#pragma unroll
        for (int ks = 0; ks < 2; ks++) {
            uint32_t ah[2][4], al[2][4];
#pragma unroll
            for (int fm = 0; fm < 2; fm++) {
                ldmx4(ah[fm], cur + K2_SAH + aoff[fm] + ks * 32);
                ldmx4(al[fm], cur + K2_SAL + aoff[fm] + ks * 32);
            }
#pragma unroll
            for (int p = 0; p < 6; p++) {
                uint32_t rh4[4], rl4[4];
                ldmx4(rh4, cur + K2_SBH + boff[p] + ks * 32);
                ldmx4(rl4, cur + K2_SBL + boff[p] + ks * 32);
#pragma unroll
                for (int fm = 0; fm < 2; fm++) {
                    mma16816(acc[fm][p*2+0], ah[fm], rh4 + 0);
                    mma16816(acc[fm][p*2+0], ah[fm], rl4 + 0);
                    mma16816(acc[fm][p*2+0], al[fm], rh4 + 0);
                    mma16816(acc[fm][p*2+1], ah[fm], rh4 + 2);
                    mma16816(acc[fm][p*2+1], ah[fm], rl4 + 2);
                    mma16816(acc[fm][p*2+1], al[fm], rh4 + 2);
                }
            }
        }

        if (have_next) {
            uint32_t h[4], lo[4];
            pack2(v0.x, v0.y, h[0], lo[0]); pack2(v0.z, v0.w, h[1], lo[1]);
            pack2(v1.x, v1.y, h[2], lo[2]); pack2(v1.z, v1.w, h[3], lo[3]);
            uint32_t ad = nxt + K2_SAH + arow * K2_BST + aq * 16;
            asm volatile("st.shared.v4.b32 [%0], {%1,%2,%3,%4};" :: "r"(ad), "r"(h[0]), "r"(h[1]), "r"(h[2]), "r"(h[3]) : "memory");
            asm volatile("st.shared.v4.b32 [%0], {%1,%2,%3,%4};" :: "r"(ad + (K2_SAL - K2_SAH)), "r"(lo[0]), "r"(lo[1]), "r"(lo[2]), "r"(lo[3]) : "memory");
            CP_WAIT0();
            __syncthreads();
        }
    }

    // ---- epilogue: iou + g_cag -> h, c ----
#pragma unroll
    for (int fm = 0; fm < 2; fm++)
#pragma unroll
        for (int rh = 0; rh < 2; rh++) {
            int node = nb + wm * 32 + fm * 16 + (l >> 2) + rh * 8;
            if (node >= NN) continue;
            const float* ib = iou_in + (size_t)node * NOUT;
#pragma unroll
            for (int g = 0; g < 4; g++) {
                int col = (wn * 4 + g) * 8 + (l & 3) * 2;
                float2 ii = *(const float2*)(ib + col);
                float2 oo = *(const float2*)(ib + HH + col);
                float2 uu = *(const float2*)(ib + 2 * HH + col);
                float2 bi = *(const float2*)(ba + col);
                float2 bo = *(const float2*)(ba + HH + col);
                float2 bu = *(const float2*)(ba + 2 * HH + col);
                float2 cg = *(const float2*)(g_cag + (size_t)node * HH + col);
                float hv[2], cv[2];
#pragma unroll
                for (int e = 0; e < 2; e++) {
                    float iv = acc[fm][g*3+0][rh*2+e] + ((e) ? ii.y + bi.y : ii.x + bi.x);
                    float ov = acc[fm][g*3+1][rh*2+e] + ((e) ? oo.y + bo.y : oo.x + bo.x);
                    float uv = acc[fm][g*3+2][rh*2+e] + ((e) ? uu.y + bu.y : uu.x + bu.x);
                    float c  = sigm(iv) * tanhf(uv) + ((e) ? cg.y : cg.x);
                    cv[e] = c;
                    hv[e] = sigm(ov) * tanhf(c);
                }
                *(float2*)(out + (size_t)node * HH + col) = make_float2(hv[0], hv[1]);
                *(float2*)(out + (size_t)NN * HH + (size_t)node * HH + col) = make_float2(cv[0], cv[1]);
            }
        }
}

// ---------------- launch ----------------
extern "C" void kernel_launch(void* const* d_in, const int* in_sizes, int n_in,
                              void* d_out, int out_size) {
    const float* nh     = (const float*)d_in[0];
    const float* ncv    = (const float*)d_in[1];
    const float* f_in   = (const float*)d_in[2];
    const float* iou_in = (const float*)d_in[3];
    const float* Uf     = (const float*)d_in[4];
    const float* bf     = (const float*)d_in[5];
    const float* Ua     = (const float*)d_in[6];
    const float* ba     = (const float*)d_in[7];
    float* out = (float*)d_out;

    prep_weights<<<2048, 256>>>(Uf, Ua);

    cudaFuncSetAttribute(k1_caggr, cudaFuncAttributeMaxDynamicSharedMemorySize, K1_SMEM);
    cudaFuncSetAttribute(k2_iou,   cudaFuncAttributeMaxDynamicSharedMemorySize, K2_SMEM);

    const int grid = (NN + 95) / 96;   // 1042
    k1_caggr<<<grid, 384, K1_SMEM>>>(nh, ncv, f_in, bf);
    k2_iou<<<grid, 384, K2_SMEM>>>(nh, iou_in, ba, out);
}

// round 10
// speedup vs baseline: 1.1236x; 1.1236x over previous
#include <cuda_runtime.h>
#include <cuda_bf16.h>
#include <cstdint>

#define NN   100000
#define DEG  8
#define HH   128
#define KTOT 1024          // DEG*HH
#define NOUT 384           // 3*HH

// ---------------- device scratch ----------------
__device__ float g_cag[(size_t)NN * HH];                       // 51.2 MB
__device__ __align__(16) __nv_bfloat16 g_w1hi[DEG * HH * HH];  // Uf^T  [d][n][k]
__device__ __align__(16) __nv_bfloat16 g_w1lo[DEG * HH * HH];
__device__ __align__(16) __nv_bfloat16 g_w2hi[NOUT * KTOT];    // Ua^T  [n'][k] interleaved
__device__ __align__(16) __nv_bfloat16 g_w2lo[NOUT * KTOT];

// ---------------- helpers ----------------
static __device__ __forceinline__ uint32_t smem_u32(const void* p) {
    uint32_t a;
    asm("{ .reg .u64 t; cvta.to.shared.u64 t, %1; cvt.u32.u64 %0, t; }" : "=r"(a) : "l"(p));
    return a;
}
static __device__ __forceinline__ void ldmx4(uint32_t r[4], uint32_t addr) {
    asm volatile("ldmatrix.sync.aligned.m8n8.x4.shared.b16 {%0,%1,%2,%3}, [%4];"
                 : "=r"(r[0]), "=r"(r[1]), "=r"(r[2]), "=r"(r[3]) : "r"(addr));
}
static __device__ __forceinline__ void mma16816(float c[4], const uint32_t a[4], const uint32_t b[2]) {
    asm volatile("mma.sync.aligned.m16n8k16.row.col.f32.bf16.bf16.f32 "
                 "{%0,%1,%2,%3},{%4,%5,%6,%7},{%8,%9},{%0,%1,%2,%3};"
                 : "+f"(c[0]), "+f"(c[1]), "+f"(c[2]), "+f"(c[3])
                 : "r"(a[0]), "r"(a[1]), "r"(a[2]), "r"(a[3]), "r"(b[0]), "r"(b[1]));
}
static __device__ __forceinline__ void cp16(uint32_t dst, const void* src) {
    asm volatile("cp.async.cg.shared.global [%0], [%1], 16;"
                 :: "r"(dst), "l"(__cvta_generic_to_global(src)) : "memory");
}
#define CP_COMMIT() asm volatile("cp.async.commit_group;" ::: "memory")
#define CP_WAIT0()  asm volatile("cp.async.wait_group 0;" ::: "memory")

static __device__ __forceinline__ float sigm(float x) { return 1.f / (1.f + __expf(-x)); }
static __device__ __forceinline__ void split_bf16(float x, uint32_t& h, uint32_t& l) {
    __nv_bfloat16 hb = __float2bfloat16(x);
    __nv_bfloat16 lb = __float2bfloat16(x - __bfloat162float(hb));
    h = (uint32_t)__bfloat16_as_ushort(hb);
    l = (uint32_t)__bfloat16_as_ushort(lb);
}
static __device__ __forceinline__ void pack2(float a, float b, uint32_t& ph, uint32_t& pl) {
    uint32_t ha, la, hb, lb;
    split_bf16(a, ha, la); split_bf16(b, hb, lb);
    ph = ha | (hb << 16);
    pl = la | (lb << 16);
}

// ---------------- prep ----------------
__global__ void prep_weights(const float* __restrict__ Uf, const float* __restrict__ Ua) {
    int t = blockIdx.x * blockDim.x + threadIdx.x;
    if (t < DEG * HH * HH) {                 // W1: [d][n][k] = Uf[d][k][n]
        int k = t & 127, n = (t >> 7) & 127, d = t >> 14;
        float v = Uf[((size_t)d * HH + k) * HH + n];
        uint32_t h, l; split_bf16(v, h, l);
        g_w1hi[t] = __ushort_as_bfloat16((unsigned short)h);
        g_w1lo[t] = __ushort_as_bfloat16((unsigned short)l);
        return;
    }
    int u = t - DEG * HH * HH;
    if (u < NOUT * KTOT) {                   // W2: n' = grp*24 + ch*8 + c8
        int k = u & 1023, np = u >> 10;
        int grp = np / 24, rem = np - grp * 24;
        int ch = rem >> 3, c8 = rem & 7;
        int col = grp * 8 + c8;
        int d = k >> 7, h = k & 127;
        float v = Ua[((size_t)d * HH + h) * NOUT + ch * HH + col];
        uint32_t hh_, ll_; split_bf16(v, hh_, ll_);
        g_w2hi[u] = __ushort_as_bfloat16((unsigned short)hh_);
        g_w2lo[u] = __ushort_as_bfloat16((unsigned short)ll_);
    }
}

// =====================================================================
// Kernel 1: f/c_aggr.  256 thr (8 warps 2m x 4n), M=64, N=128, warp 32x32.
// MMA order: terms-outer (same-acc reuse distance 4).
// =====================================================================
#define K1_BST   80
#define K1_SBH   0
#define K1_SBL   10240
#define K1_SAH   20480
#define K1_SAL   25600
#define K1_STAGE 30720
#define K1_SMEM  61440

__global__ __launch_bounds__(256, 2)
void k1_caggr(const float* __restrict__ nh, const float* __restrict__ ncv,
              const float* __restrict__ f_in, const float* __restrict__ bf) {
    extern __shared__ unsigned char smb[];
    const uint32_t sb = smem_u32(smb);
    const int tid = threadIdx.x, wid = tid >> 5, l = tid & 31;
    const int wm = wid & 1, wn = wid >> 1;
    const int nb = blockIdx.x * 64;

    uint32_t aoff[2], boff[2];
#pragma unroll
    for (int fm = 0; fm < 2; fm++)
        aoff[fm] = (uint32_t)(wm * 32 + fm * 16 + (l & 15)) * K1_BST + (uint32_t)(l >> 4) * 16;
#pragma unroll
    for (int p = 0; p < 2; p++)
        boff[p] = (uint32_t)(wn * 32 + p * 16 + (l & 7) + ((l >> 4) ? 8 : 0)) * K1_BST
                + (uint32_t)((l >> 3) & 1) * 16;

    float accf[2][4][4], cag[2][4][4];
#pragma unroll
    for (int a = 0; a < 2; a++)
#pragma unroll
        for (int b = 0; b < 4; b++)
#pragma unroll
            for (int c = 0; c < 4; c++) { accf[a][b][c] = 0.f; cag[a][b][c] = 0.f; }

    const int arow = tid >> 2, aq = tid & 3;
    const int anode = nb + arow;
    const float* asrc = nh + (size_t)anode * KTOT + aq * 8;

    // ---- prologue: chunk 0 ----
    {
#pragma unroll
        for (int i = 0; i < 2; i++) {
            int idx = tid + i * 256;            // 0..511
            int r = idx >> 2, g = idx & 3;
            uint32_t doff = sb + r * K1_BST + g * 16;
            cp16(doff + K1_SBH, (const char*)(g_w1hi + (size_t)r * HH) + g * 16);
            cp16(doff + K1_SBL, (const char*)(g_w1lo + (size_t)r * HH) + g * 16);
        }
        CP_COMMIT();
        float4 v0 = make_float4(0,0,0,0), v1 = v0;
        if (anode < NN) { v0 = *(const float4*)(asrc); v1 = *(const float4*)(asrc + 4); }
        uint32_t h[4], lo[4];
        pack2(v0.x, v0.y, h[0], lo[0]); pack2(v0.z, v0.w, h[1], lo[1]);
        pack2(v1.x, v1.y, h[2], lo[2]); pack2(v1.z, v1.w, h[3], lo[3]);
        uint32_t ad = sb + K1_SAH + arow * K1_BST + aq * 16;
        asm volatile("st.shared.v4.b32 [%0], {%1,%2,%3,%4};" :: "r"(ad), "r"(h[0]), "r"(h[1]), "r"(h[2]), "r"(h[3]) : "memory");
        asm volatile("st.shared.v4.b32 [%0], {%1,%2,%3,%4};" :: "r"(ad + (K1_SAL - K1_SAH)), "r"(lo[0]), "r"(lo[1]), "r"(lo[2]), "r"(lo[3]) : "memory");
        CP_WAIT0();
        __syncthreads();
    }

    for (int kc = 0; kc < 32; kc++) {
        const uint32_t cur = sb + (kc & 1) * K1_STAGE;
        const uint32_t nxt = sb + ((kc + 1) & 1) * K1_STAGE;
        const bool have_next = (kc < 31);

        float4 v0, v1;
        if (have_next) {
            v0 = make_float4(0,0,0,0); v1 = v0;
            if (anode < NN) {
                v0 = *(const float4*)(asrc + (kc + 1) * 32);
                v1 = *(const float4*)(asrc + (kc + 1) * 32 + 4);
            }
            int dn = (kc + 1) >> 2, sl = (kc + 1) & 3;
#pragma unroll
            for (int i = 0; i < 2; i++) {
                int idx = tid + i * 256;
                int r = idx >> 2, g = idx & 3;
                uint32_t doff = nxt + r * K1_BST + g * 16;
                cp16(doff + K1_SBH, (const char*)(g_w1hi + ((size_t)dn * HH + r) * HH) + sl * 64 + g * 16);
                cp16(doff + K1_SBL, (const char*)(g_w1lo + ((size_t)dn * HH + r) * HH) + sl * 64 + g * 16);
            }
            CP_COMMIT();
        }

        // ---- compute chunk kc (terms-outer MMA order) ----
#pragma unroll
        for (int ks = 0; ks < 2; ks++) {
            uint32_t ah[2][4], al[2][4];
#pragma unroll
            for (int fm = 0; fm < 2; fm++) {
                ldmx4(ah[fm], cur + K1_SAH + aoff[fm] + ks * 32);
                ldmx4(al[fm], cur + K1_SAL + aoff[fm] + ks * 32);
            }
#pragma unroll
            for (int p = 0; p < 2; p++) {
                uint32_t rh4[4], rl4[4];
                ldmx4(rh4, cur + K1_SBH + boff[p] + ks * 32);
                ldmx4(rl4, cur + K1_SBL + boff[p] + ks * 32);
                // term hh
                mma16816(accf[0][p*2+0], ah[0], rh4 + 0);
                mma16816(accf[0][p*2+1], ah[0], rh4 + 2);
                mma16816(accf[1][p*2+0], ah[1], rh4 + 0);
                mma16816(accf[1][p*2+1], ah[1], rh4 + 2);
                // term hl
                mma16816(accf[0][p*2+0], ah[0], rl4 + 0);
                mma16816(accf[0][p*2+1], ah[0], rl4 + 2);
                mma16816(accf[1][p*2+0], ah[1], rl4 + 0);
                mma16816(accf[1][p*2+1], ah[1], rl4 + 2);
                // term lh
                mma16816(accf[0][p*2+0], al[0], rh4 + 0);
                mma16816(accf[0][p*2+1], al[0], rh4 + 2);
                mma16816(accf[1][p*2+0], al[1], rh4 + 0);
                mma16816(accf[1][p*2+1], al[1], rh4 + 2);
            }
        }

        // ---- f epilogue at end of each d ----
        if ((kc & 3) == 3) {
            const int d = kc >> 2;
#pragma unroll
            for (int fm = 0; fm < 2; fm++)
#pragma unroll
                for (int rh = 0; rh < 2; rh++) {
                    int node = nb + wm * 32 + fm * 16 + (l >> 2) + rh * 8;
                    if (node < NN) {
#pragma unroll
                        for (int fn = 0; fn < 4; fn++) {
                            int col = wn * 32 + fn * 8 + (l & 3) * 2;
                            float2 fi  = *(const float2*)(f_in + (size_t)node * HH + col);
                            float2 nc2 = *(const float2*)(ncv + ((size_t)node * DEG + d) * HH + col);
                            float2 bf2 = *(const float2*)(bf + d * HH + col);
                            cag[fm][fn][rh*2+0] += sigm(accf[fm][fn][rh*2+0] + bf2.x + fi.x) * nc2.x;
                            cag[fm][fn][rh*2+1] += sigm(accf[fm][fn][rh*2+1] + bf2.y + fi.y) * nc2.y;
                        }
                    }
#pragma unroll
                    for (int fn = 0; fn < 4; fn++) {
                        accf[fm][fn][rh*2+0] = 0.f;
                        accf[fm][fn][rh*2+1] = 0.f;
                    }
                }
        }

        if (have_next) {
            uint32_t h[4], lo[4];
            pack2(v0.x, v0.y, h[0], lo[0]); pack2(v0.z, v0.w, h[1], lo[1]);
            pack2(v1.x, v1.y, h[2], lo[2]); pack2(v1.z, v1.w, h[3], lo[3]);
            uint32_t ad = nxt + K1_SAH + arow * K1_BST + aq * 16;
            asm volatile("st.shared.v4.b32 [%0], {%1,%2,%3,%4};" :: "r"(ad), "r"(h[0]), "r"(h[1]), "r"(h[2]), "r"(h[3]) : "memory");
            asm volatile("st.shared.v4.b32 [%0], {%1,%2,%3,%4};" :: "r"(ad + (K1_SAL - K1_SAH)), "r"(lo[0]), "r"(lo[1]), "r"(lo[2]), "r"(lo[3]) : "memory");
            CP_WAIT0();
            __syncthreads();
        }
    }

    // ---- store c_aggr ----
#pragma unroll
    for (int fm = 0; fm < 2; fm++)
#pragma unroll
        for (int rh = 0; rh < 2; rh++) {
            int node = nb + wm * 32 + fm * 16 + (l >> 2) + rh * 8;
            if (node >= NN) continue;
#pragma unroll
            for (int fn = 0; fn < 4; fn++) {
                int col = wn * 32 + fn * 8 + (l & 3) * 2;
                *(float2*)(g_cag + (size_t)node * HH + col) =
                    make_float2(cag[fm][fn][rh*2+0], cag[fm][fn][rh*2+1]);
            }
        }
}

// =====================================================================
// Kernel 2: iou GEMM + epilogue.  256 thr (8 warps 2m x 4n), M=64,
// N=192 (half of interleaved 384; blockIdx.y picks half), warp 32x48.
// MMA order: terms-outer.
// =====================================================================
#define K2_BST   80
#define K2_SBH   0
#define K2_SBL   15360
#define K2_SAH   30720
#define K2_SAL   35840
#define K2_STAGE 40960
#define K2_SMEM  81920

__global__ __launch_bounds__(256, 2)
void k2_iou(const float* __restrict__ nh, const float* __restrict__ iou_in,
            const float* __restrict__ ba, float* __restrict__ out) {
    extern __shared__ unsigned char smb[];
    const uint32_t sb = smem_u32(smb);
    const int tid = threadIdx.x, wid = tid >> 5, l = tid & 31;
    const int wm = wid & 1, wn = wid >> 1;
    const int nb = blockIdx.x * 64;
    const int nhalf = blockIdx.y;               // 0 or 1
    const int brow0 = nhalf * 192;

    uint32_t aoff[2], boff[3];
#pragma unroll
    for (int fm = 0; fm < 2; fm++)
        aoff[fm] = (uint32_t)(wm * 32 + fm * 16 + (l & 15)) * K2_BST + (uint32_t)(l >> 4) * 16;
#pragma unroll
    for (int p = 0; p < 3; p++)
        boff[p] = (uint32_t)(wn * 48 + p * 16 + (l & 7) + ((l >> 4) ? 8 : 0)) * K2_BST
                + (uint32_t)((l >> 3) & 1) * 16;

    float acc[2][6][4];
#pragma unroll
    for (int a = 0; a < 2; a++)
#pragma unroll
        for (int b = 0; b < 6; b++)
#pragma unroll
            for (int c = 0; c < 4; c++) acc[a][b][c] = 0.f;

    const int arow = tid >> 2, aq = tid & 3;
    const int anode = nb + arow;
    const float* asrc = nh + (size_t)anode * KTOT + aq * 8;

    // ---- prologue: chunk 0 ----
    {
#pragma unroll
        for (int i = 0; i < 3; i++) {
            int idx = tid + i * 256;            // 0..767
            int r = idx >> 2, g = idx & 3;
            uint32_t doff = sb + r * K2_BST + g * 16;
            cp16(doff + K2_SBH, (const char*)(g_w2hi + (size_t)(brow0 + r) * KTOT) + g * 16);
            cp16(doff + K2_SBL, (const char*)(g_w2lo + (size_t)(brow0 + r) * KTOT) + g * 16);
        }
        CP_COMMIT();
        float4 v0 = make_float4(0,0,0,0), v1 = v0;
        if (anode < NN) { v0 = *(const float4*)(asrc); v1 = *(const float4*)(asrc + 4); }
        uint32_t h[4], lo[4];
        pack2(v0.x, v0.y, h[0], lo[0]); pack2(v0.z, v0.w, h[1], lo[1]);
        pack2(v1.x, v1.y, h[2], lo[2]); pack2(v1.z, v1.w, h[3], lo[3]);
        uint32_t ad = sb + K2_SAH + arow * K2_BST + aq * 16;
        asm volatile("st.shared.v4.b32 [%0], {%1,%2,%3,%4};" :: "r"(ad), "r"(h[0]), "r"(h[1]), "r"(h[2]), "r"(h[3]) : "memory");
        asm volatile("st.shared.v4.b32 [%0], {%1,%2,%3,%4};" :: "r"(ad + (K2_SAL - K2_SAH)), "r"(lo[0]), "r"(lo[1]), "r"(lo[2]), "r"(lo[3]) : "memory");
        CP_WAIT0();
        __syncthreads();
    }

    for (int kc = 0; kc < 32; kc++) {
        const uint32_t cur = sb + (kc & 1) * K2_STAGE;
        const uint32_t nxt = sb + ((kc + 1) & 1) * K2_STAGE;
        const bool have_next = (kc < 31);

        float4 v0, v1;
        if (have_next) {
            v0 = make_float4(0,0,0,0); v1 = v0;
            if (anode < NN) {
                v0 = *(const float4*)(asrc + (kc + 1) * 32);
                v1 = *(const float4*)(asrc + (kc + 1) * 32 + 4);
            }
#pragma unroll
            for (int i = 0; i < 3; i++) {
                int idx = tid + i * 256;
                int r = idx >> 2, g = idx & 3;
                uint32_t doff = nxt + r * K2_BST + g * 16;
                cp16(doff + K2_SBH, (const char*)(g_w2hi + (size_t)(brow0 + r) * KTOT) + (kc + 1) * 64 + g * 16);
                cp16(doff + K2_SBL, (const char*)(g_w2lo + (size_t)(brow0 + r) * KTOT) + (kc + 1) * 64 + g * 16);
            }
            CP_COMMIT();
        }

        // ---- compute (terms-outer MMA order) ----
#pragma unroll
        for (int ks = 0; ks < 2; ks++) {
            uint32_t ah[2][4], al[2][4];
#pragma unroll
            for (int fm = 0; fm < 2; fm++) {
                ldmx4(ah[fm], cur + K2_SAH + aoff[fm] + ks * 32);
                ldmx4(al[fm], cur + K2_SAL + aoff[fm] + ks * 32);
            }
#pragma unroll
            for (int p = 0; p < 3; p++) {
                uint32_t rh4[4], rl4[4];
                ldmx4(rh4, cur + K2_SBH + boff[p] + ks * 32);
                ldmx4(rl4, cur + K2_SBL + boff[p] + ks * 32);
                // term hh
                mma16816(acc[0][p*2+0], ah[0], rh4 + 0);
                mma16816(acc[0][p*2+1], ah[0], rh4 + 2);
                mma16816(acc[1][p*2+0], ah[1], rh4 + 0);
                mma16816(acc[1][p*2+1], ah[1], rh4 + 2);
                // term hl
                mma16816(acc[0][p*2+0], ah[0], rl4 + 0);
                mma16816(acc[0][p*2+1], ah[0], rl4 + 2);
                mma16816(acc[1][p*2+0], ah[1], rl4 + 0);
                mma16816(acc[1][p*2+1], ah[1], rl4 + 2);
                // term lh
                mma16816(acc[0][p*2+0], al[0], rh4 + 0);
                mma16816(acc[0][p*2+1], al[0], rh4 + 2);
                mma16816(acc[1][p*2+0], al[1], rh4 + 0);
                mma16816(acc[1][p*2+1], al[1], rh4 + 2);
            }
        }

        if (have_next) {
            uint32_t h[4], lo[4];
            pack2(v0.x, v0.y, h[0], lo[0]); pack2(v0.z, v0.w, h[1], lo[1]);
            pack2(v1.x, v1.y, h[2], lo[2]); pack2(v1.z, v1.w, h[3], lo[3]);
            uint32_t ad = nxt + K2_SAH + arow * K2_BST + aq * 16;
            asm volatile("st.shared.v4.b32 [%0], {%1,%2,%3,%4};" :: "r"(ad), "r"(h[0]), "r"(h[1]), "r"(h[2]), "r"(h[3]) : "memory");
            asm volatile("st.shared.v4.b32 [%0], {%1,%2,%3,%4};" :: "r"(ad + (K2_SAL - K2_SAH)), "r"(lo[0]), "r"(lo[1]), "r"(lo[2]), "r"(lo[3]) : "memory");
            CP_WAIT0();
            __syncthreads();
        }
    }

    // ---- epilogue: this CTA owns output cols [nhalf*64, nhalf*64+64) ----
#pragma unroll
    for (int fm = 0; fm < 2; fm++)
#pragma unroll
        for (int rh = 0; rh < 2; rh++) {
            int node = nb + wm * 32 + fm * 16 + (l >> 2) + rh * 8;
            if (node >= NN) continue;
            const float* ib = iou_in + (size_t)node * NOUT;
#pragma unroll
            for (int g = 0; g < 2; g++) {
                int col = (nhalf * 8 + wn * 2 + g) * 8 + (l & 3) * 2;
                float2 ii = *(const float2*)(ib + col);
                float2 oo = *(const float2*)(ib + HH + col);
                float2 uu = *(const float2*)(ib + 2 * HH + col);
                float2 bi = *(const float2*)(ba + col);
                float2 bo = *(const float2*)(ba + HH + col);
                float2 bu = *(const float2*)(ba + 2 * HH + col);
                float2 cg = *(const float2*)(g_cag + (size_t)node * HH + col);
                float hv[2], cv[2];
#pragma unroll
                for (int e = 0; e < 2; e++) {
                    float iv = acc[fm][g*3+0][rh*2+e] + ((e) ? ii.y + bi.y : ii.x + bi.x);
                    float ov = acc[fm][g*3+1][rh*2+e] + ((e) ? oo.y + bo.y : oo.x + bo.x);
                    float uv = acc[fm][g*3+2][rh*2+e] + ((e) ? uu.y + bu.y : uu.x + bu.x);
                    float c  = sigm(iv) * tanhf(uv) + ((e) ? cg.y : cg.x);
                    cv[e] = c;
                    hv[e] = sigm(ov) * tanhf(c);
                }
                *(float2*)(out + (size_t)node * HH + col) = make_float2(hv[0], hv[1]);
                *(float2*)(out + (size_t)NN * HH + (size_t)node * HH + col) = make_float2(cv[0], cv[1]);
            }
        }
}

// ---------------- launch ----------------
extern "C" void kernel_launch(void* const* d_in, const int* in_sizes, int n_in,
                              void* d_out, int out_size) {
    const float* nh     = (const float*)d_in[0];
    const float* ncv    = (const float*)d_in[1];
    const float* f_in   = (const float*)d_in[2];
    const float* iou_in = (const float*)d_in[3];
    const float* Uf     = (const float*)d_in[4];
    const float* bf     = (const float*)d_in[5];
    const float* Ua     = (const float*)d_in[6];
    const float* ba     = (const float*)d_in[7];
    float* out = (float*)d_out;

    prep_weights<<<2048, 256>>>(Uf, Ua);

    cudaFuncSetAttribute(k1_caggr, cudaFuncAttributeMaxDynamicSharedMemorySize, K1_SMEM);
    cudaFuncSetAttribute(k2_iou,   cudaFuncAttributeMaxDynamicSharedMemorySize, K2_SMEM);

    k1_caggr<<<(NN + 63) / 64, 256, K1_SMEM>>>(nh, ncv, f_in, bf);
    dim3 g2((NN + 63) / 64, 2);
    k2_iou<<<g2, 256, K2_SMEM>>>(nh, iou_in, ba, out);
}

// round 11
// speedup vs baseline: 1.2983x; 1.1555x over previous
#include <cuda_runtime.h>
#include <cuda_fp16.h>
#include <cstdint>

#define NN   100000
#define DEG  8
#define HH   128
#define KTOT 1024          // DEG*HH
#define NOUT 384           // 3*HH

// ---------------- device scratch ----------------
__device__ float g_cag[(size_t)NN * HH];                  // 51.2 MB
__device__ __align__(16) __half g_w1hi[DEG * HH * HH];    // Uf^T  [d][n][k]  fp16 hi
__device__ __align__(16) __half g_w1lo[DEG * HH * HH];    //                  fp16 lo
__device__ __align__(16) __half g_w2hi[NOUT * KTOT];      // Ua^T  [n'][k] interleaved
__device__ __align__(16) __half g_w2lo[NOUT * KTOT];

// ---------------- helpers ----------------
static __device__ __forceinline__ uint32_t smem_u32(const void* p) {
    uint32_t a;
    asm("{ .reg .u64 t; cvta.to.shared.u64 t, %1; cvt.u32.u64 %0, t; }" : "=r"(a) : "l"(p));
    return a;
}
static __device__ __forceinline__ void ldmx4(uint32_t r[4], uint32_t addr) {
    asm volatile("ldmatrix.sync.aligned.m8n8.x4.shared.b16 {%0,%1,%2,%3}, [%4];"
                 : "=r"(r[0]), "=r"(r[1]), "=r"(r[2]), "=r"(r[3]) : "r"(addr));
}
static __device__ __forceinline__ void mma16816(float c[4], const uint32_t a[4], const uint32_t b[2]) {
    asm volatile("mma.sync.aligned.m16n8k16.row.col.f32.f16.f16.f32 "
                 "{%0,%1,%2,%3},{%4,%5,%6,%7},{%8,%9},{%0,%1,%2,%3};"
                 : "+f"(c[0]), "+f"(c[1]), "+f"(c[2]), "+f"(c[3])
                 : "r"(a[0]), "r"(a[1]), "r"(a[2]), "r"(a[3]), "r"(b[0]), "r"(b[1]));
}
static __device__ __forceinline__ void cp16(uint32_t dst, const void* src) {
    asm volatile("cp.async.cg.shared.global [%0], [%1], 16;"
                 :: "r"(dst), "l"(__cvta_generic_to_global(src)) : "memory");
}
#define CP_COMMIT() asm volatile("cp.async.commit_group;" ::: "memory")
#define CP_WAIT0()  asm volatile("cp.async.wait_group 0;" ::: "memory")

static __device__ __forceinline__ float sigm(float x) { return 1.f / (1.f + __expf(-x)); }
// pack two f32 -> one u32 of fp16x2 (element0 in low half)
static __device__ __forceinline__ uint32_t pack2h(float a, float b) {
    __half2 h = __floats2half2_rn(a, b);
    return *reinterpret_cast<uint32_t*>(&h);
}

// ---------------- prep: transpose + fp16 hi/lo split of weights ----------------
__global__ void prep_weights(const float* __restrict__ Uf, const float* __restrict__ Ua) {
    int t = blockIdx.x * blockDim.x + threadIdx.x;
    if (t < DEG * HH * HH) {                 // W1: [d][n][k] = Uf[d][k][n]
        int k = t & 127, n = (t >> 7) & 127, d = t >> 14;
        float v = Uf[((size_t)d * HH + k) * HH + n];
        __half hb = __float2half_rn(v);
        __half lb = __float2half_rn(v - __half2float(hb));
        g_w1hi[t] = hb;
        g_w1lo[t] = lb;
        return;
    }
    int u = t - DEG * HH * HH;
    if (u < NOUT * KTOT) {                   // W2: n' = grp*24 + ch*8 + c8
        int k = u & 1023, np = u >> 10;
        int grp = np / 24, rem = np - grp * 24;
        int ch = rem >> 3, c8 = rem & 7;
        int col = grp * 8 + c8;
        int d = k >> 7, h = k & 127;
        float v = Ua[((size_t)d * HH + h) * NOUT + ch * HH + col];
        __half hb = __float2half_rn(v);
        __half lb = __float2half_rn(v - __half2float(hb));
        g_w2hi[u] = hb;
        g_w2lo[u] = lb;
    }
}

// =====================================================================
// Kernel 1: f/c_aggr.  256 thr (8 warps 2m x 4n), M=64, N=128, warp 32x32.
// A plain fp16, B fp16 hi/lo (2-term).
// =====================================================================
#define K1_BST   80
#define K1_SBH   0          // B hi 128*80 = 10240
#define K1_SBL   10240
#define K1_SA    20480      // A 64*80 = 5120
#define K1_STAGE 25600
#define K1_SMEM  51200

__global__ __launch_bounds__(256, 2)
void k1_caggr(const float* __restrict__ nh, const float* __restrict__ ncv,
              const float* __restrict__ f_in, const float* __restrict__ bf) {
    extern __shared__ unsigned char smb[];
    const uint32_t sb = smem_u32(smb);
    const int tid = threadIdx.x, wid = tid >> 5, l = tid & 31;
    const int wm = wid & 1, wn = wid >> 1;
    const int nb = blockIdx.x * 64;

    uint32_t aoff[2], boff[2];
#pragma unroll
    for (int fm = 0; fm < 2; fm++)
        aoff[fm] = (uint32_t)(wm * 32 + fm * 16 + (l & 15)) * K1_BST + (uint32_t)(l >> 4) * 16;
#pragma unroll
    for (int p = 0; p < 2; p++)
        boff[p] = (uint32_t)(wn * 32 + p * 16 + (l & 7) + ((l >> 4) ? 8 : 0)) * K1_BST
                + (uint32_t)((l >> 3) & 1) * 16;

    float accf[2][4][4], cag[2][4][4];
#pragma unroll
    for (int a = 0; a < 2; a++)
#pragma unroll
        for (int b = 0; b < 4; b++)
#pragma unroll
            for (int c = 0; c < 4; c++) { accf[a][b][c] = 0.f; cag[a][b][c] = 0.f; }

    const int arow = tid >> 2, aq = tid & 3;
    const int anode = nb + arow;
    const float* asrc = nh + (size_t)anode * KTOT + aq * 8;

    // ---- prologue: chunk 0 ----
    {
#pragma unroll
        for (int i = 0; i < 2; i++) {
            int idx = tid + i * 256;            // 0..511
            int r = idx >> 2, g = idx & 3;
            uint32_t doff = sb + r * K1_BST + g * 16;
            cp16(doff + K1_SBH, (const char*)(g_w1hi + (size_t)r * HH) + g * 16);
            cp16(doff + K1_SBL, (const char*)(g_w1lo + (size_t)r * HH) + g * 16);
        }
        CP_COMMIT();
        float4 v0 = make_float4(0,0,0,0), v1 = v0;
        if (anode < NN) { v0 = *(const float4*)(asrc); v1 = *(const float4*)(asrc + 4); }
        uint32_t h0 = pack2h(v0.x, v0.y), h1 = pack2h(v0.z, v0.w);
        uint32_t h2 = pack2h(v1.x, v1.y), h3 = pack2h(v1.z, v1.w);
        uint32_t ad = sb + K1_SA + arow * K1_BST + aq * 16;
        asm volatile("st.shared.v4.b32 [%0], {%1,%2,%3,%4};" :: "r"(ad), "r"(h0), "r"(h1), "r"(h2), "r"(h3) : "memory");
        CP_WAIT0();
        __syncthreads();
    }

    for (int kc = 0; kc < 32; kc++) {
        const uint32_t cur = sb + (kc & 1) * K1_STAGE;
        const uint32_t nxt = sb + ((kc + 1) & 1) * K1_STAGE;
        const bool have_next = (kc < 31);

        float4 v0, v1;
        if (have_next) {
            v0 = make_float4(0,0,0,0); v1 = v0;
            if (anode < NN) {
                v0 = *(const float4*)(asrc + (kc + 1) * 32);
                v1 = *(const float4*)(asrc + (kc + 1) * 32 + 4);
            }
            int dn = (kc + 1) >> 2, sl = (kc + 1) & 3;
#pragma unroll
            for (int i = 0; i < 2; i++) {
                int idx = tid + i * 256;
                int r = idx >> 2, g = idx & 3;
                uint32_t doff = nxt + r * K1_BST + g * 16;
                cp16(doff + K1_SBH, (const char*)(g_w1hi + ((size_t)dn * HH + r) * HH) + sl * 64 + g * 16);
                cp16(doff + K1_SBL, (const char*)(g_w1lo + ((size_t)dn * HH + r) * HH) + sl * 64 + g * 16);
            }
            CP_COMMIT();
        }

        // ---- compute chunk kc (2-term: A*Bhi + A*Blo) ----
#pragma unroll
        for (int ks = 0; ks < 2; ks++) {
            uint32_t ah[2][4];
#pragma unroll
            for (int fm = 0; fm < 2; fm++)
                ldmx4(ah[fm], cur + K1_SA + aoff[fm] + ks * 32);
#pragma unroll
            for (int p = 0; p < 2; p++) {
                uint32_t rh4[4], rl4[4];
                ldmx4(rh4, cur + K1_SBH + boff[p] + ks * 32);
                ldmx4(rl4, cur + K1_SBL + boff[p] + ks * 32);
                mma16816(accf[0][p*2+0], ah[0], rh4 + 0);
                mma16816(accf[0][p*2+1], ah[0], rh4 + 2);
                mma16816(accf[1][p*2+0], ah[1], rh4 + 0);
                mma16816(accf[1][p*2+1], ah[1], rh4 + 2);
                mma16816(accf[0][p*2+0], ah[0], rl4 + 0);
                mma16816(accf[0][p*2+1], ah[0], rl4 + 2);
                mma16816(accf[1][p*2+0], ah[1], rl4 + 0);
                mma16816(accf[1][p*2+1], ah[1], rl4 + 2);
            }
        }

        // ---- f epilogue at end of each d ----
        if ((kc & 3) == 3) {
            const int d = kc >> 2;
#pragma unroll
            for (int fm = 0; fm < 2; fm++)
#pragma unroll
                for (int rh = 0; rh < 2; rh++) {
                    int node = nb + wm * 32 + fm * 16 + (l >> 2) + rh * 8;
                    if (node < NN) {
#pragma unroll
                        for (int fn = 0; fn < 4; fn++) {
                            int col = wn * 32 + fn * 8 + (l & 3) * 2;
                            float2 fi  = *(const float2*)(f_in + (size_t)node * HH + col);
                            float2 nc2 = *(const float2*)(ncv + ((size_t)node * DEG + d) * HH + col);
                            float2 bf2 = *(const float2*)(bf + d * HH + col);
                            cag[fm][fn][rh*2+0] += sigm(accf[fm][fn][rh*2+0] + bf2.x + fi.x) * nc2.x;
                            cag[fm][fn][rh*2+1] += sigm(accf[fm][fn][rh*2+1] + bf2.y + fi.y) * nc2.y;
                        }
                    }
#pragma unroll
                    for (int fn = 0; fn < 4; fn++) {
                        accf[fm][fn][rh*2+0] = 0.f;
                        accf[fm][fn][rh*2+1] = 0.f;
                    }
                }
        }

        if (have_next) {
            uint32_t h0 = pack2h(v0.x, v0.y), h1 = pack2h(v0.z, v0.w);
            uint32_t h2 = pack2h(v1.x, v1.y), h3 = pack2h(v1.z, v1.w);
            uint32_t ad = nxt + K1_SA + arow * K1_BST + aq * 16;
            asm volatile("st.shared.v4.b32 [%0], {%1,%2,%3,%4};" :: "r"(ad), "r"(h0), "r"(h1), "r"(h2), "r"(h3) : "memory");
            CP_WAIT0();
            __syncthreads();
        }
    }

    // ---- store c_aggr ----
#pragma unroll
    for (int fm = 0; fm < 2; fm++)
#pragma unroll
        for (int rh = 0; rh < 2; rh++) {
            int node = nb + wm * 32 + fm * 16 + (l >> 2) + rh * 8;
            if (node >= NN) continue;
#pragma unroll
            for (int fn = 0; fn < 4; fn++) {
                int col = wn * 32 + fn * 8 + (l & 3) * 2;
                *(float2*)(g_cag + (size_t)node * HH + col) =
                    make_float2(cag[fm][fn][rh*2+0], cag[fm][fn][rh*2+1]);
            }
        }
}

// =====================================================================
// Kernel 2: iou GEMM + epilogue.  256 thr (8 warps 2m x 4n), M=64,
// N=192 (half of interleaved 384; blockIdx.y picks half), warp 32x48.
// A plain fp16, B fp16 hi/lo (2-term).
// =====================================================================
#define K2_BST   80
#define K2_SBH   0          // B hi 192*80 = 15360
#define K2_SBL   15360
#define K2_SA    30720      // A 64*80 = 5120
#define K2_STAGE 35840
#define K2_SMEM  71680

__global__ __launch_bounds__(256, 2)
void k2_iou(const float* __restrict__ nh, const float* __restrict__ iou_in,
            const float* __restrict__ ba, float* __restrict__ out) {
    extern __shared__ unsigned char smb[];
    const uint32_t sb = smem_u32(smb);
    const int tid = threadIdx.x, wid = tid >> 5, l = tid & 31;
    const int wm = wid & 1, wn = wid >> 1;
    const int nb = blockIdx.x * 64;
    const int nhalf = blockIdx.y;               // 0 or 1
    const int brow0 = nhalf * 192;

    uint32_t aoff[2], boff[3];
#pragma unroll
    for (int fm = 0; fm < 2; fm++)
        aoff[fm] = (uint32_t)(wm * 32 + fm * 16 + (l & 15)) * K2_BST + (uint32_t)(l >> 4) * 16;
#pragma unroll
    for (int p = 0; p < 3; p++)
        boff[p] = (uint32_t)(wn * 48 + p * 16 + (l & 7) + ((l >> 4) ? 8 : 0)) * K2_BST
                + (uint32_t)((l >> 3) & 1) * 16;

    float acc[2][6][4];
#pragma unroll
    for (int a = 0; a < 2; a++)
#pragma unroll
        for (int b = 0; b < 6; b++)
#pragma unroll
            for (int c = 0; c < 4; c++) acc[a][b][c] = 0.f;

    const int arow = tid >> 2, aq = tid & 3;
    const int anode = nb + arow;
    const float* asrc = nh + (size_t)anode * KTOT + aq * 8;

    // ---- prologue: chunk 0 ----
    {
#pragma unroll
        for (int i = 0; i < 3; i++) {
            int idx = tid + i * 256;            // 0..767
            int r = idx >> 2, g = idx & 3;
            uint32_t doff = sb + r * K2_BST + g * 16;
            cp16(doff + K2_SBH, (const char*)(g_w2hi + (size_t)(brow0 + r) * KTOT) + g * 16);
            cp16(doff + K2_SBL, (const char*)(g_w2lo + (size_t)(brow0 + r) * KTOT) + g * 16);
        }
        CP_COMMIT();
        float4 v0 = make_float4(0,0,0,0), v1 = v0;
        if (anode < NN) { v0 = *(const float4*)(asrc); v1 = *(const float4*)(asrc + 4); }
        uint32_t h0 = pack2h(v0.x, v0.y), h1 = pack2h(v0.z, v0.w);
        uint32_t h2 = pack2h(v1.x, v1.y), h3 = pack2h(v1.z, v1.w);
        uint32_t ad = sb + K2_SA + arow * K2_BST + aq * 16;
        asm volatile("st.shared.v4.b32 [%0], {%1,%2,%3,%4};" :: "r"(ad), "r"(h0), "r"(h1), "r"(h2), "r"(h3) : "memory");
        CP_WAIT0();
        __syncthreads();
    }

    for (int kc = 0; kc < 32; kc++) {
        const uint32_t cur = sb + (kc & 1) * K2_STAGE;
        const uint32_t nxt = sb + ((kc + 1) & 1) * K2_STAGE;
        const bool have_next = (kc < 31);

        float4 v0, v1;
        if (have_next) {
            v0 = make_float4(0,0,0,0); v1 = v0;
            if (anode < NN) {
                v0 = *(const float4*)(asrc + (kc + 1) * 32);
                v1 = *(const float4*)(asrc + (kc + 1) * 32 + 4);
            }
#pragma unroll
            for (int i = 0; i < 3; i++) {
                int idx = tid + i * 256;
                int r = idx >> 2, g = idx & 3;
                uint32_t doff = nxt + r * K2_BST + g * 16;
                cp16(doff + K2_SBH, (const char*)(g_w2hi + (size_t)(brow0 + r) * KTOT) + (kc + 1) * 64 + g * 16);
                cp16(doff + K2_SBL, (const char*)(g_w2lo + (size_t)(brow0 + r) * KTOT) + (kc + 1) * 64 + g * 16);
            }
            CP_COMMIT();
        }

        // ---- compute (2-term: A*Bhi + A*Blo) ----
#pragma unroll
        for (int ks = 0; ks < 2; ks++) {
            uint32_t ah[2][4];
#pragma unroll
            for (int fm = 0; fm < 2; fm++)
                ldmx4(ah[fm], cur + K2_SA + aoff[fm] + ks * 32);
#pragma unroll
            for (int p = 0; p < 3; p++) {
                uint32_t rh4[4], rl4[4];
                ldmx4(rh4, cur + K2_SBH + boff[p] + ks * 32);
                ldmx4(rl4, cur + K2_SBL + boff[p] + ks * 32);
                mma16816(acc[0][p*2+0], ah[0], rh4 + 0);
                mma16816(acc[0][p*2+1], ah[0], rh4 + 2);
                mma16816(acc[1][p*2+0], ah[1], rh4 + 0);
                mma16816(acc[1][p*2+1], ah[1], rh4 + 2);
                mma16816(acc[0][p*2+0], ah[0], rl4 + 0);
                mma16816(acc[0][p*2+1], ah[0], rl4 + 2);
                mma16816(acc[1][p*2+0], ah[1], rl4 + 0);
                mma16816(acc[1][p*2+1], ah[1], rl4 + 2);
            }
        }

        if (have_next) {
            uint32_t h0 = pack2h(v0.x, v0.y), h1 = pack2h(v0.z, v0.w);
            uint32_t h2 = pack2h(v1.x, v1.y), h3 = pack2h(v1.z, v1.w);
            uint32_t ad = nxt + K2_SA + arow * K2_BST + aq * 16;
            asm volatile("st.shared.v4.b32 [%0], {%1,%2,%3,%4};" :: "r"(ad), "r"(h0), "r"(h1), "r"(h2), "r"(h3) : "memory");
            CP_WAIT0();
            __syncthreads();
        }
    }

    // ---- epilogue: this CTA owns output cols [nhalf*64, nhalf*64+64) ----
#pragma unroll
    for (int fm = 0; fm < 2; fm++)
#pragma unroll
        for (int rh = 0; rh < 2; rh++) {
            int node = nb + wm * 32 + fm * 16 + (l >> 2) + rh * 8;
            if (node >= NN) continue;
            const float* ib = iou_in + (size_t)node * NOUT;
#pragma unroll
            for (int g = 0; g < 2; g++) {
                int col = (nhalf * 8 + wn * 2 + g) * 8 + (l & 3) * 2;
                float2 ii = *(const float2*)(ib + col);
                float2 oo = *(const float2*)(ib + HH + col);
                float2 uu = *(const float2*)(ib + 2 * HH + col);
                float2 bi = *(const float2*)(ba + col);
                float2 bo = *(const float2*)(ba + HH + col);
                float2 bu = *(const float2*)(ba + 2 * HH + col);
                float2 cg = *(const float2*)(g_cag + (size_t)node * HH + col);
                float hv[2], cv[2];
#pragma unroll
                for (int e = 0; e < 2; e++) {
                    float iv = acc[fm][g*3+0][rh*2+e] + ((e) ? ii.y + bi.y : ii.x + bi.x);
                    float ov = acc[fm][g*3+1][rh*2+e] + ((e) ? oo.y + bo.y : oo.x + bo.x);
                    float uv = acc[fm][g*3+2][rh*2+e] + ((e) ? uu.y + bu.y : uu.x + bu.x);
                    float c  = sigm(iv) * tanhf(uv) + ((e) ? cg.y : cg.x);
                    cv[e] = c;
                    hv[e] = sigm(ov) * tanhf(c);
                }
                *(float2*)(out + (size_t)node * HH + col) = make_float2(hv[0], hv[1]);
                *(float2*)(out + (size_t)NN * HH + (size_t)node * HH + col) = make_float2(cv[0], cv[1]);
            }
        }
}

// ---------------- launch ----------------
extern "C" void kernel_launch(void* const* d_in, const int* in_sizes, int n_in,
                              void* d_out, int out_size) {
    const float* nh     = (const float*)d_in[0];
    const float* ncv    = (const float*)d_in[1];
    const float* f_in   = (const float*)d_in[2];
    const float* iou_in = (const float*)d_in[3];
    const float* Uf     = (const float*)d_in[4];
    const float* bf     = (const float*)d_in[5];
    const float* Ua     = (const float*)d_in[6];
    const float* ba     = (const float*)d_in[7];
    float* out = (float*)d_out;

    prep_weights<<<2048, 256>>>(Uf, Ua);

    cudaFuncSetAttribute(k1_caggr, cudaFuncAttributeMaxDynamicSharedMemorySize, K1_SMEM);
    cudaFuncSetAttribute(k2_iou,   cudaFuncAttributeMaxDynamicSharedMemorySize, K2_SMEM);

    k1_caggr<<<(NN + 63) / 64, 256, K1_SMEM>>>(nh, ncv, f_in, bf);
    dim3 g2((NN + 63) / 64, 2);
    k2_iou<<<g2, 256, K2_SMEM>>>(nh, iou_in, ba, out);
}